// round 16
// baseline (speedup 1.0000x reference)
#include <cuda_runtime.h>
#include <cuda_fp16.h>
#include <math.h>

#define Bv 2
#define Tv 2048
#define Dv 2048
#define HKv 16
#define HVv 32
#define DKv 128
#define DVv 128
#define KEY_DIM 2048
#define VALUE_DIM 4096
#define CONV_DIM 8192
#define KCONV 4
#define EPSv 1e-6f
#define BT (Bv*Tv)

// ---------------- scratch (device globals; no allocation allowed) ----------
__device__ float  g_mixed [BT*CONV_DIM];     // x @ w_qkv
__device__ float  g_mixedc[BT*CONV_DIM];     // conv+silu output (v-part only used)
__device__ float  g_z     [BT*VALUE_DIM];    // x @ w_z
__device__ float  g_qn    [BT*KEY_DIM];      // l2norm'd q
__device__ float  g_kn    [BT*KEY_DIM];      // l2norm'd k
__device__ float  g_gg    [BT*HVv];          // decay log g
__device__ float  g_beta  [BT*HVv];          // beta
__device__ float  g_core  [BT*VALUE_DIM];    // scan output (f32)
__device__ __half g_xh    [BT*Dv];           // fp16 x
__device__ __half g_wqkvh [Dv*CONV_DIM];     // fp16 w_qkv
__device__ __half g_wzh   [Dv*VALUE_DIM];    // fp16 w_z
__device__ __half g_wouth [VALUE_DIM*Dv];    // fp16 w_out
__device__ __half g_coreh [BT*VALUE_DIM];    // fp16 gated core

// ================= helpers =================================================
__device__ __forceinline__ unsigned smem_u32(const void* p) {
    unsigned a;
    asm("{ .reg .u64 t; cvta.to.shared.u64 t, %1; cvt.u32.u64 %0, t; }" : "=r"(a) : "l"(p));
    return a;
}
#define CP_ASYNC16(dst, src) asm volatile("cp.async.cg.shared.global [%0], [%1], 16;" :: "r"(dst), "l"(src))
#define CP_COMMIT()          asm volatile("cp.async.commit_group;")
#define CP_WAIT(n)           asm volatile("cp.async.wait_group %0;" :: "n"(n))

__device__ __forceinline__ void ldsm_x4(unsigned* r, unsigned addr) {
    asm volatile("ldmatrix.sync.aligned.m8n8.x4.shared.b16 {%0,%1,%2,%3}, [%4];"
                 : "=r"(r[0]), "=r"(r[1]), "=r"(r[2]), "=r"(r[3]) : "r"(addr));
}
__device__ __forceinline__ void ldsm_x4_t(unsigned* r, unsigned addr) {
    asm volatile("ldmatrix.sync.aligned.m8n8.x4.trans.shared.b16 {%0,%1,%2,%3}, [%4];"
                 : "=r"(r[0]), "=r"(r[1]), "=r"(r[2]), "=r"(r[3]) : "r"(addr));
}
__device__ __forceinline__ void mma_f16(float* c, const unsigned* a, const unsigned* b) {
    asm volatile(
        "mma.sync.aligned.m16n8k16.row.col.f32.f16.f16.f32 "
        "{%0,%1,%2,%3}, {%4,%5,%6,%7}, {%8,%9}, {%0,%1,%2,%3};"
        : "+f"(c[0]), "+f"(c[1]), "+f"(c[2]), "+f"(c[3])
        : "r"(a[0]), "r"(a[1]), "r"(a[2]), "r"(a[3]), "r"(b[0]), "r"(b[1]));
}

// ---- packed f32x2 ops (sm_100+ PTX)
typedef unsigned long long ull;
__device__ __forceinline__ ull pack2(float lo, float hi) {
    ull r; asm("mov.b64 %0, {%1, %2};" : "=l"(r) : "f"(lo), "f"(hi)); return r;
}
__device__ __forceinline__ void unpack2(float& lo, float& hi, ull v) {
    asm("mov.b64 {%0, %1}, %2;" : "=f"(lo), "=f"(hi) : "l"(v));
}
__device__ __forceinline__ ull mul2(ull a, ull b) {
    ull r; asm("mul.rn.f32x2 %0, %1, %2;" : "=l"(r) : "l"(a), "l"(b)); return r;
}
__device__ __forceinline__ ull add2(ull a, ull b) {
    ull r; asm("add.rn.f32x2 %0, %1, %2;" : "=l"(r) : "l"(a), "l"(b)); return r;
}
__device__ __forceinline__ ull fma2(ull a, ull b, ull c) {
    ull r; asm("fma.rn.f32x2 %0, %1, %2, %3;" : "=l"(r) : "l"(a), "l"(b), "l"(c)); return r;
}

// ================= f32 -> f16 conversion (8 elems / thread) ================
__global__ void f2h_kernel(const float* __restrict__ src,
                           __half* __restrict__ dst, int n8)
{
    int i = blockIdx.x * blockDim.x + threadIdx.x;
    if (i >= n8) return;
    float4 a = ((const float4*)src)[2 * i];
    float4 b = ((const float4*)src)[2 * i + 1];
    __half2 h[4];
    h[0] = __floats2half2_rn(a.x, a.y);
    h[1] = __floats2half2_rn(a.z, a.w);
    h[2] = __floats2half2_rn(b.x, b.y);
    h[3] = __floats2half2_rn(b.z, b.w);
    ((uint4*)dst)[i] = *(uint4*)h;
}

// ================= fp16 mma.sync GEMM: C[M,N] = A[M,K] @ B[K,N] ============
// BK=64, 3-stage cp.async pipeline (deep prefetch, 2 CTAs/SM).
// A smem: [128][72] halves (144B rows). B smem: [64][136] halves.
#define LDA_H 72
#define LDB_H 136
#define A_HS (128*LDA_H)             // 9216 halves / stage
#define B_HS (64*LDB_H)              // 8704 halves / stage
#define ST_H (A_HS + B_HS)           // 17920 halves = 35840 B
#define GEMM_SMEM (3*ST_H*2)         // 107520 B -> still 2 CTAs/SM (215KB<228KB)

__global__ void __launch_bounds__(256, 2) hgemm_kernel(
    const __half* __restrict__ A, const __half* __restrict__ B,
    float* __restrict__ C, int M, int N, int K)
{
    extern __shared__ __align__(16) __half hsm[];
    const unsigned sb = smem_u32(hsm);
    const int tid = threadIdx.x;
    const int wid = tid >> 5;
    const int lane = tid & 31;
    const int bm = blockIdx.y * 128;
    const int bn = blockIdx.x * 128;
    const int NT_K = K >> 6;

    const int warpM = (wid & 1) * 64;
    const int warpN = (wid >> 1) * 32;
    const int g = lane >> 2;
    const int tg = lane & 3;

    const __half* gA = A + (size_t)bm * K;
    const __half* gB = B + bn;

    auto load_tile = [&](int s, int t) {
        const int k0 = t << 6;
        const unsigned base = sb + (unsigned)s * (ST_H * 2);
        #pragma unroll
        for (int i = 0; i < 4; i++) {      // A: 128 rows x 8 chunks = 1024
            int cid = tid + i * 256;
            int row = cid >> 3, c = cid & 7;
            CP_ASYNC16(base + (row * LDA_H + c * 8) * 2,
                       gA + (size_t)row * K + k0 + c * 8);
        }
        #pragma unroll
        for (int i = 0; i < 4; i++) {      // B: 64 rows x 16 chunks = 1024
            int cid = tid + i * 256;
            int row = cid >> 4, c = cid & 15;
            CP_ASYNC16(base + (A_HS + row * LDB_H + c * 8) * 2,
                       gB + (size_t)(k0 + row) * N + c * 8);
        }
        CP_COMMIT();
    };

    const int a_row = (lane & 15);
    const int a_col = (lane >> 4) * 8;
    const int b_row = (lane & 15);
    const int b_col = (lane >> 4) * 8;

    float acc[4][4][4];
    #pragma unroll
    for (int i = 0; i < 4; i++)
        #pragma unroll
        for (int j = 0; j < 4; j++)
            #pragma unroll
            for (int e = 0; e < 4; e++) acc[i][j][e] = 0.f;

    load_tile(0, 0);
    load_tile(1, 1);

    for (int t = 0; t < NT_K; t++) {
        if (t < NT_K - 2) { CP_WAIT(1); } else { CP_WAIT(0); }
        __syncthreads();
        if (t + 2 < NT_K) load_tile((t + 2) % 3, t + 2);

        const unsigned abase = sb + (unsigned)(t % 3) * (ST_H * 2);
        const unsigned bbase = abase + A_HS * 2;

        #pragma unroll
        for (int kc = 0; kc < 4; kc++) {
            unsigned af[4][4], bf[2][4];
            #pragma unroll
            for (int mt = 0; mt < 4; mt++)
                ldsm_x4(af[mt], abase +
                    ((warpM + mt * 16 + a_row) * LDA_H + kc * 16 + a_col) * 2);
            #pragma unroll
            for (int ntp = 0; ntp < 2; ntp++)
                ldsm_x4_t(bf[ntp], bbase +
                    ((kc * 16 + b_row) * LDB_H + warpN + ntp * 16 + b_col) * 2);
            #pragma unroll
            for (int mt = 0; mt < 4; mt++)
                #pragma unroll
                for (int nt = 0; nt < 4; nt++)
                    mma_f16(acc[mt][nt], af[mt], &bf[nt >> 1][(nt & 1) * 2]);
        }
        __syncthreads();
    }

    #pragma unroll
    for (int mt = 0; mt < 4; mt++) {
        #pragma unroll
        for (int nt = 0; nt < 4; nt++) {
            int r = bm + warpM + mt * 16 + g;
            int cN = bn + warpN + nt * 8 + tg * 2;
            *(float2*)(C + (size_t)r * N + cN) = make_float2(acc[mt][nt][0], acc[mt][nt][1]);
            *(float2*)(C + (size_t)(r + 8) * N + cN) = make_float2(acc[mt][nt][2], acc[mt][nt][3]);
        }
    }
}

// ================= beta / g projections (32 rows per block) ================
__global__ __launch_bounds__(256) void proj_ba_kernel(
    const float* __restrict__ x, const float* __restrict__ w_b,
    const float* __restrict__ w_a, const float* __restrict__ dt_bias,
    const float* __restrict__ A_log)
{
    __shared__ float sx[32][64];
    const int row0 = blockIdx.x * 32;
    const int tid = threadIdx.x;
    const int col = tid & 63;
    const int isa = (col >= 32);
    const int c32 = col & 31;
    const int rg = tid >> 6;
    const float* w = isa ? w_a : w_b;

    float acc[8];
    #pragma unroll
    for (int j = 0; j < 8; j++) acc[j] = 0.f;

    for (int k0 = 0; k0 < Dv; k0 += 64) {
        __syncthreads();
        #pragma unroll
        for (int i = 0; i < 2; i++) {
            int e = (tid + i * 256) * 4;
            int r = e >> 6, c = e & 63;
            *(float4*)&sx[r][c] = *(const float4*)(x + (size_t)(row0 + r) * Dv + k0 + c);
        }
        __syncthreads();
        for (int kk = 0; kk < 64; kk++) {
            float wv = w[(k0 + kk) * HVv + c32];
            #pragma unroll
            for (int j = 0; j < 8; j++)
                acc[j] += sx[rg * 8 + j][kk] * wv;
        }
    }
    #pragma unroll
    for (int j = 0; j < 8; j++) {
        int r = row0 + rg * 8 + j;
        if (!isa) {
            g_beta[r * HVv + c32] = 1.f / (1.f + expf(-acc[j]));
        } else {
            float xsp = acc[j] + dt_bias[c32];
            float sp = (xsp > 20.f) ? xsp : log1pf(expf(xsp));
            g_gg[r * HVv + c32] = -expf(A_log[c32]) * sp;
        }
    }
}

// ================= causal conv (v channels only) + SiLU ====================
__global__ void conv_v_kernel(const float* __restrict__ conv_w)
{
    const int n4 = BT * VALUE_DIM / 4;
    int idx = blockIdx.x * blockDim.x + threadIdx.x;
    if (idx >= n4) return;
    const int c4 = idx % (VALUE_DIM / 4);
    const int bt = idx / (VALUE_DIM / 4);
    const int t = bt % Tv;
    const int coff = 2 * KEY_DIM / 4 + c4;

    float4 acc = make_float4(0.f, 0.f, 0.f, 0.f);
    #pragma unroll
    for (int k = 0; k < KCONV; k++) {
        int tt = t + k - (KCONV - 1);
        if (tt >= 0) {
            float4 m = ((const float4*)g_mixed)[(size_t)(bt + k - (KCONV - 1)) * (CONV_DIM / 4) + coff];
            float4 w = ((const float4*)conv_w)[k * (CONV_DIM / 4) + coff];
            acc.x += m.x * w.x;
            acc.y += m.y * w.y;
            acc.z += m.z * w.z;
            acc.w += m.w * w.w;
        }
    }
    acc.x = acc.x / (1.f + expf(-acc.x));
    acc.y = acc.y / (1.f + expf(-acc.y));
    acc.z = acc.z / (1.f + expf(-acc.z));
    acc.w = acc.w / (1.f + expf(-acc.w));
    ((float4*)g_mixedc)[(size_t)bt * (CONV_DIM / 4) + coff] = acc;
}

// ================= fused conv + SiLU + l2norm for q/k heads ================
__global__ void conv_qk_norm_kernel(const float* __restrict__ conv_w)
{
    const int gw = (blockIdx.x * blockDim.x + threadIdx.x) >> 5;
    const int lane = threadIdx.x & 31;
    const int bt = gw >> 5;
    const int r = gw & 31;
    const int isk = r >> 4;
    const int h = r & 15;
    const int t = bt % Tv;
    const int cbase = isk * KEY_DIM + h * DKv;

    float v[4];
    float ss = 0.f;
    #pragma unroll
    for (int i = 0; i < 4; i++) {
        const int c = cbase + lane + 32 * i;
        float acc = 0.f;
        #pragma unroll
        for (int k = 0; k < KCONV; k++) {
            int tt = t + k - (KCONV - 1);
            if (tt >= 0)
                acc += g_mixed[(size_t)(bt + k - (KCONV - 1)) * CONV_DIM + c]
                     * conv_w[k * CONV_DIM + c];
        }
        float s = acc / (1.f + expf(-acc));
        v[i] = s;
        ss += s * s;
    }
    #pragma unroll
    for (int off = 16; off > 0; off >>= 1)
        ss += __shfl_xor_sync(0xFFFFFFFFu, ss, off);
    float sc = rsqrtf(ss + EPSv);
    if (!isk) sc *= 0.08838834764831845f;
    float* dst = (isk ? g_kn : g_qn) + ((size_t)bt * HKv + h) * DKv;
    #pragma unroll
    for (int i = 0; i < 4; i++) dst[lane + 32 * i] = v[i] * sc;
}

// ================= sequential gated delta-rule scan (f32x2, 2 steps/bar) ===
__global__ __launch_bounds__(128, 1) void scan_kernel()
{
    const int unit = blockIdx.x >> 1;
    const int chalf = blockIdx.x & 1;
    const int b = unit / HVv;
    const int h = unit % HVv;
    const int kvh = h >> 1;

    const int tid = threadIdx.x;
    const int colL = tid >> 1;
    const int dhalf = tid & 1;
    const int gcol = chalf * 64 + colL;

    ull st2[32];
    #pragma unroll
    for (int i = 0; i < 32; i++) st2[i] = 0ull;

    __shared__ float sq[4][DKv];
    __shared__ float sk[4][DKv];
    __shared__ float sv[4][64];

    const size_t qkbase0 = ((size_t)(b * Tv) * HKv + kvh) * DKv;
    const size_t vbase0 = (size_t)(b * Tv) * CONV_DIM + 2 * KEY_DIM + h * DVv;
    const size_t corebase = ((size_t)(b * Tv) * HVv + h) * DVv + gcol;

    float rq0 = g_qn[qkbase0 + tid];
    float rk0 = g_kn[qkbase0 + tid];
    float rv0 = (tid < 64) ? g_mixedc[vbase0 + chalf * 64 + tid] : 0.f;
    float rg0 = g_gg[(b * Tv) * HVv + h];
    float rb0 = g_beta[(b * Tv) * HVv + h];
    float rq1 = g_qn[qkbase0 + HKv * DKv + tid];
    float rk1 = g_kn[qkbase0 + HKv * DKv + tid];
    float rv1 = (tid < 64) ? g_mixedc[vbase0 + CONV_DIM + chalf * 64 + tid] : 0.f;
    float rg1 = g_gg[(b * Tv + 1) * HVv + h];
    float rb1 = g_beta[(b * Tv + 1) * HVv + h];

    auto do_step = [&](int buf, float dec, float be, int tg2) {
        const ull dec2 = pack2(dec, dec);
        const ulonglong2* kp = (const ulonglong2*)&sk[buf][dhalf * 64];
        ull kreg[32];
        #pragma unroll
        for (int j = 0; j < 16; j++) {
            ulonglong2 kk = kp[j];
            kreg[2 * j] = kk.x;
            kreg[2 * j + 1] = kk.y;
        }
        ull kva = 0ull, kvb = 0ull, kvc = 0ull, kvd = 0ull;
        #pragma unroll
        for (int i = 0; i < 32; i += 4) {
            st2[i]     = mul2(st2[i],     dec2);
            st2[i + 1] = mul2(st2[i + 1], dec2);
            st2[i + 2] = mul2(st2[i + 2], dec2);
            st2[i + 3] = mul2(st2[i + 3], dec2);
            kva = fma2(kreg[i],     st2[i],     kva);
            kvb = fma2(kreg[i + 1], st2[i + 1], kvb);
            kvc = fma2(kreg[i + 2], st2[i + 2], kvc);
            kvd = fma2(kreg[i + 3], st2[i + 3], kvd);
        }
        ull kvp = add2(add2(kva, kvb), add2(kvc, kvd));
        float klo, khi;
        unpack2(klo, khi, kvp);
        float kv = klo + khi;
        kv += __shfl_xor_sync(0xFFFFFFFFu, kv, 1);

        const float vt = sv[buf][colL];
        const float delta = (vt - kv) * be;
        const ull delta2 = pack2(delta, delta);

        const ulonglong2* qp = (const ulonglong2*)&sq[buf][dhalf * 64];
        ull oa = 0ull, ob = 0ull, oc = 0ull, od = 0ull;
        #pragma unroll
        for (int j = 0; j < 8; j++) {
            ulonglong2 q0 = qp[2 * j];
            ulonglong2 q1 = qp[2 * j + 1];
            int i = 4 * j;
            st2[i]     = fma2(kreg[i],     delta2, st2[i]);
            st2[i + 1] = fma2(kreg[i + 1], delta2, st2[i + 1]);
            st2[i + 2] = fma2(kreg[i + 2], delta2, st2[i + 2]);
            st2[i + 3] = fma2(kreg[i + 3], delta2, st2[i + 3]);
            oa = fma2(q0.x, st2[i],     oa);
            ob = fma2(q0.y, st2[i + 1], ob);
            oc = fma2(q1.x, st2[i + 2], oc);
            od = fma2(q1.y, st2[i + 3], od);
        }
        ull op = add2(add2(oa, ob), add2(oc, od));
        float olo, ohi;
        unpack2(olo, ohi, op);
        float out = olo + ohi;
        out += __shfl_xor_sync(0xFFFFFFFFu, out, 1);
        if (dhalf == 0)
            g_core[corebase + (size_t)tg2 * (HVv * DVv)] = out;
    };

    for (int t = 0; t < Tv; t += 2) {
        const int b0 = ((t >> 1) & 1) * 2;
        const int b1 = b0 + 1;
        sq[b0][tid] = rq0; sk[b0][tid] = rk0;
        sq[b1][tid] = rq1; sk[b1][tid] = rk1;
        if (tid < 64) { sv[b0][tid] = rv0; sv[b1][tid] = rv1; }
        const float gt0 = rg0, be0 = rb0, gt1 = rg1, be1 = rb1;
        __syncthreads();

        const int tn0 = (t + 2 < Tv) ? (t + 2) : t;
        const int tn1 = (t + 3 < Tv) ? (t + 3) : t;
        {
            const size_t qkb0 = qkbase0 + (size_t)tn0 * (HKv * DKv);
            const size_t qkb1 = qkbase0 + (size_t)tn1 * (HKv * DKv);
            rq0 = g_qn[qkb0 + tid]; rk0 = g_kn[qkb0 + tid];
            rq1 = g_qn[qkb1 + tid]; rk1 = g_kn[qkb1 + tid];
            if (tid < 64) {
                rv0 = g_mixedc[vbase0 + (size_t)tn0 * CONV_DIM + chalf * 64 + tid];
                rv1 = g_mixedc[vbase0 + (size_t)tn1 * CONV_DIM + chalf * 64 + tid];
            }
            rg0 = g_gg[(b * Tv + tn0) * HVv + h];
            rb0 = g_beta[(b * Tv + tn0) * HVv + h];
            rg1 = g_gg[(b * Tv + tn1) * HVv + h];
            rb1 = g_beta[(b * Tv + tn1) * HVv + h];
        }

        const float dec0 = expf(gt0);
        const float dec1 = expf(gt1);
        do_step(b0, dec0, be0, t);
        do_step(b1, dec1, be1, t + 1);
    }
}

// ================= gated RMS norm epilogue (writes fp16) ====================
__global__ void gate_kernel(const float* __restrict__ norm_w)
{
    const int row = (blockIdx.x * blockDim.x + threadIdx.x) >> 5;
    const int lane = threadIdx.x & 31;
    const int bt = row / HVv;
    const int h = row % HVv;

    const float* c = g_core + (size_t)row * DVv;
    __half* ch = g_coreh + (size_t)row * DVv;
    const float* z = g_z + (size_t)bt * VALUE_DIM + h * DVv;

    float v[4];
    float ss = 0.f;
    #pragma unroll
    for (int i = 0; i < 4; i++) {
        v[i] = c[lane + 32 * i];
        ss += v[i] * v[i];
    }
    #pragma unroll
    for (int off = 16; off > 0; off >>= 1)
        ss += __shfl_xor_sync(0xFFFFFFFFu, ss, off);
    float rinv = rsqrtf(ss * (1.f / 128.f) + EPSv);
    #pragma unroll
    for (int i = 0; i < 4; i++) {
        int idx = lane + 32 * i;
        float zv = z[idx];
        float sig = 1.f / (1.f + expf(-zv));
        ch[idx] = __float2half_rn(norm_w[idx] * v[i] * rinv * zv * sig);
    }
}

// ================= launch ==================================================
extern "C" void kernel_launch(void* const* d_in, const int* in_sizes, int n_in,
                              void* d_out, int out_size)
{
    const float* x       = (const float*)d_in[0];
    const float* w_qkv   = (const float*)d_in[1];
    const float* w_z     = (const float*)d_in[2];
    const float* w_b     = (const float*)d_in[3];
    const float* w_a     = (const float*)d_in[4];
    const float* conv_w  = (const float*)d_in[5];
    const float* dt_bias = (const float*)d_in[6];
    const float* A_log   = (const float*)d_in[7];
    const float* norm_w  = (const float*)d_in[8];
    const float* w_out   = (const float*)d_in[9];
    float* out = (float*)d_out;

    float *mixed, *z, *core;
    __half *xh, *wqkvh, *wzh, *wouth, *coreh;
    cudaGetSymbolAddress((void**)&mixed, g_mixed);
    cudaGetSymbolAddress((void**)&z,     g_z);
    cudaGetSymbolAddress((void**)&core,  g_core);
    cudaGetSymbolAddress((void**)&xh,    g_xh);
    cudaGetSymbolAddress((void**)&wqkvh, g_wqkvh);
    cudaGetSymbolAddress((void**)&wzh,   g_wzh);
    cudaGetSymbolAddress((void**)&wouth, g_wouth);
    cudaGetSymbolAddress((void**)&coreh, g_coreh);

    cudaFuncSetAttribute(hgemm_kernel,
                         cudaFuncAttributeMaxDynamicSharedMemorySize, GEMM_SMEM);

    static cudaStream_t s1 = nullptr, s2 = nullptr;
    static cudaEvent_t ev0 = nullptr, ev_fx = nullptr, ev_wq = nullptr,
                       ev_g1 = nullptr, ev_cv = nullptr, ev_z = nullptr, ev_ba = nullptr;
    if (s1 == nullptr) {
        cudaStreamCreateWithFlags(&s1, cudaStreamNonBlocking);
        cudaStreamCreateWithFlags(&s2, cudaStreamNonBlocking);
        cudaEventCreateWithFlags(&ev0,   cudaEventDisableTiming);
        cudaEventCreateWithFlags(&ev_fx, cudaEventDisableTiming);
        cudaEventCreateWithFlags(&ev_wq, cudaEventDisableTiming);
        cudaEventCreateWithFlags(&ev_g1, cudaEventDisableTiming);
        cudaEventCreateWithFlags(&ev_cv, cudaEventDisableTiming);
        cudaEventCreateWithFlags(&ev_z,  cudaEventDisableTiming);
        cudaEventCreateWithFlags(&ev_ba, cudaEventDisableTiming);
    }

    // ---- s0: fork origin
    cudaEventRecord(ev0, 0);

    // ---- s2 (forked at t=0): w_qkv -> fp16, then proj_ba + w_out conversion
    cudaStreamWaitEvent(s2, ev0, 0);
    f2h_kernel<<<(Dv * CONV_DIM / 8 + 255) / 256, 256, 0, s2>>>(w_qkv, wqkvh, Dv * CONV_DIM / 8);
    cudaEventRecord(ev_wq, s2);
    proj_ba_kernel<<<BT / 32, 256, 0, s2>>>(x, w_b, w_a, dt_bias, A_log);
    f2h_kernel<<<(VALUE_DIM * Dv / 8 + 255) / 256, 256, 0, s2>>>(w_out, wouth, VALUE_DIM * Dv / 8);
    cudaEventRecord(ev_ba, s2);

    // ---- s0: x -> fp16
    f2h_kernel<<<(BT * Dv / 8 + 255) / 256, 256>>>(x, xh, BT * Dv / 8);
    cudaEventRecord(ev_fx, 0);

    // ---- s1 (fork): w_z -> fp16, GEMM2 (z)
    cudaStreamWaitEvent(s1, ev_fx, 0);
    f2h_kernel<<<(Dv * VALUE_DIM / 8 + 255) / 256, 256, 0, s1>>>(w_z, wzh, Dv * VALUE_DIM / 8);
    hgemm_kernel<<<dim3(VALUE_DIM / 128, BT / 128), 256, GEMM_SMEM, s1>>>(xh, wzh, z, BT, VALUE_DIM, Dv);
    cudaEventRecord(ev_z, s1);

    // ---- s0 main chain: GEMM1
    cudaStreamWaitEvent(0, ev_wq, 0);
    hgemm_kernel<<<dim3(CONV_DIM / 128, BT / 128), 256, GEMM_SMEM>>>(xh, wqkvh, mixed, BT, CONV_DIM, Dv);
    cudaEventRecord(ev_g1, 0);

    // ---- s2: conv_v concurrent with conv_qk_norm (both DRAM-bound)
    cudaStreamWaitEvent(s2, ev_g1, 0);
    conv_v_kernel<<<(BT * VALUE_DIM / 4 + 255) / 256, 256, 0, s2>>>(conv_w);
    cudaEventRecord(ev_cv, s2);

    // ---- s0: conv_qk_norm, then scan (needs conv_v + g/beta too)
    conv_qk_norm_kernel<<<BT * 32 * 32 / 256, 256>>>(conv_w);

    cudaStreamWaitEvent(0, ev_cv, 0);
    cudaStreamWaitEvent(0, ev_ba, 0);
    scan_kernel<<<Bv * HVv * 2, 128>>>();

    cudaStreamWaitEvent(0, ev_z, 0);           // gate needs z
    gate_kernel<<<BT * HVv / 8, 256>>>(norm_w);

    hgemm_kernel<<<dim3(Dv / 128, BT / 128), 256, GEMM_SMEM>>>(coreh, wouth, out, BT, Dv, VALUE_DIM);
}

// round 17
// speedup vs baseline: 1.0225x; 1.0225x over previous
#include <cuda_runtime.h>
#include <cuda_fp16.h>
#include <math.h>

#define Bv 2
#define Tv 2048
#define Dv 2048
#define HKv 16
#define HVv 32
#define DKv 128
#define DVv 128
#define KEY_DIM 2048
#define VALUE_DIM 4096
#define CONV_DIM 8192
#define KCONV 4
#define EPSv 1e-6f
#define BT (Bv*Tv)

// ---------------- scratch (device globals; no allocation allowed) ----------
__device__ float  g_mixed [BT*CONV_DIM];     // x @ w_qkv
__device__ float  g_mixedc[BT*CONV_DIM];     // conv+silu output (v-part only used)
__device__ float  g_z     [BT*VALUE_DIM];    // x @ w_z
__device__ float  g_qn    [BT*KEY_DIM];      // l2norm'd q
__device__ float  g_kn    [BT*KEY_DIM];      // l2norm'd k
__device__ float  g_gg    [BT*HVv];          // decay log g
__device__ float  g_beta  [BT*HVv];          // beta
__device__ float  g_core  [BT*VALUE_DIM];    // scan output (f32)
__device__ __half g_xh    [BT*Dv];           // fp16 x
__device__ __half g_wqkvh [Dv*CONV_DIM];     // fp16 w_qkv
__device__ __half g_wzh   [Dv*VALUE_DIM];    // fp16 w_z
__device__ __half g_wouth [VALUE_DIM*Dv];    // fp16 w_out
__device__ __half g_coreh [BT*VALUE_DIM];    // fp16 gated core

// ================= helpers =================================================
__device__ __forceinline__ unsigned smem_u32(const void* p) {
    unsigned a;
    asm("{ .reg .u64 t; cvta.to.shared.u64 t, %1; cvt.u32.u64 %0, t; }" : "=r"(a) : "l"(p));
    return a;
}
#define CP_ASYNC16(dst, src) asm volatile("cp.async.cg.shared.global [%0], [%1], 16;" :: "r"(dst), "l"(src))
#define CP_COMMIT()          asm volatile("cp.async.commit_group;")
#define CP_WAIT(n)           asm volatile("cp.async.wait_group %0;" :: "n"(n))

__device__ __forceinline__ void ldsm_x4(unsigned* r, unsigned addr) {
    asm volatile("ldmatrix.sync.aligned.m8n8.x4.shared.b16 {%0,%1,%2,%3}, [%4];"
                 : "=r"(r[0]), "=r"(r[1]), "=r"(r[2]), "=r"(r[3]) : "r"(addr));
}
__device__ __forceinline__ void ldsm_x4_t(unsigned* r, unsigned addr) {
    asm volatile("ldmatrix.sync.aligned.m8n8.x4.trans.shared.b16 {%0,%1,%2,%3}, [%4];"
                 : "=r"(r[0]), "=r"(r[1]), "=r"(r[2]), "=r"(r[3]) : "r"(addr));
}
__device__ __forceinline__ void mma_f16(float* c, const unsigned* a, const unsigned* b) {
    asm volatile(
        "mma.sync.aligned.m16n8k16.row.col.f32.f16.f16.f32 "
        "{%0,%1,%2,%3}, {%4,%5,%6,%7}, {%8,%9}, {%0,%1,%2,%3};"
        : "+f"(c[0]), "+f"(c[1]), "+f"(c[2]), "+f"(c[3])
        : "r"(a[0]), "r"(a[1]), "r"(a[2]), "r"(a[3]), "r"(b[0]), "r"(b[1]));
}

// ---- packed f32x2 ops (sm_100+ PTX)
typedef unsigned long long ull;
__device__ __forceinline__ ull pack2(float lo, float hi) {
    ull r; asm("mov.b64 %0, {%1, %2};" : "=l"(r) : "f"(lo), "f"(hi)); return r;
}
__device__ __forceinline__ void unpack2(float& lo, float& hi, ull v) {
    asm("mov.b64 {%0, %1}, %2;" : "=f"(lo), "=f"(hi) : "l"(v));
}
__device__ __forceinline__ ull mul2(ull a, ull b) {
    ull r; asm("mul.rn.f32x2 %0, %1, %2;" : "=l"(r) : "l"(a), "l"(b)); return r;
}
__device__ __forceinline__ ull add2(ull a, ull b) {
    ull r; asm("add.rn.f32x2 %0, %1, %2;" : "=l"(r) : "l"(a), "l"(b)); return r;
}
__device__ __forceinline__ ull fma2(ull a, ull b, ull c) {
    ull r; asm("fma.rn.f32x2 %0, %1, %2, %3;" : "=l"(r) : "l"(a), "l"(b), "l"(c)); return r;
}

// ================= f32 -> f16 conversion (8 elems / thread) ================
__global__ void f2h_kernel(const float* __restrict__ src,
                           __half* __restrict__ dst, int n8)
{
    int i = blockIdx.x * blockDim.x + threadIdx.x;
    if (i >= n8) return;
    float4 a = ((const float4*)src)[2 * i];
    float4 b = ((const float4*)src)[2 * i + 1];
    __half2 h[4];
    h[0] = __floats2half2_rn(a.x, a.y);
    h[1] = __floats2half2_rn(a.z, a.w);
    h[2] = __floats2half2_rn(b.x, b.y);
    h[3] = __floats2half2_rn(b.z, b.w);
    ((uint4*)dst)[i] = *(uint4*)h;
}

// ================= fp16 mma.sync GEMM: C[M,N] = A[M,K] @ B[K,N] ============
// BK=64, 2-stage cp.async pipeline (proven round-15 config).
// A smem: [128][72] halves (144B rows). B smem: [64][136] halves.
#define LDA_H 72
#define LDB_H 136
#define A_HS (128*LDA_H)             // 9216 halves / stage
#define B_HS (64*LDB_H)              // 8704 halves / stage
#define ST_H (A_HS + B_HS)           // 17920 halves = 35840 B
#define GEMM_SMEM (2*ST_H*2)         // 71680 B -> 2 CTAs/SM

__global__ void __launch_bounds__(256, 2) hgemm_kernel(
    const __half* __restrict__ A, const __half* __restrict__ B,
    float* __restrict__ C, int M, int N, int K)
{
    extern __shared__ __align__(16) __half hsm[];
    const unsigned sb = smem_u32(hsm);
    const int tid = threadIdx.x;
    const int wid = tid >> 5;
    const int lane = tid & 31;
    const int bm = blockIdx.y * 128;
    const int bn = blockIdx.x * 128;
    const int NT_K = K >> 6;

    const int warpM = (wid & 1) * 64;
    const int warpN = (wid >> 1) * 32;
    const int g = lane >> 2;
    const int tg = lane & 3;

    const __half* gA = A + (size_t)bm * K;
    const __half* gB = B + bn;

    auto load_tile = [&](int s, int t) {
        const int k0 = t << 6;
        const unsigned base = sb + (unsigned)s * (ST_H * 2);
        #pragma unroll
        for (int i = 0; i < 4; i++) {      // A: 128 rows x 8 chunks = 1024
            int cid = tid + i * 256;
            int row = cid >> 3, c = cid & 7;
            CP_ASYNC16(base + (row * LDA_H + c * 8) * 2,
                       gA + (size_t)row * K + k0 + c * 8);
        }
        #pragma unroll
        for (int i = 0; i < 4; i++) {      // B: 64 rows x 16 chunks = 1024
            int cid = tid + i * 256;
            int row = cid >> 4, c = cid & 15;
            CP_ASYNC16(base + (A_HS + row * LDB_H + c * 8) * 2,
                       gB + (size_t)(k0 + row) * N + c * 8);
        }
        CP_COMMIT();
    };

    const int a_row = (lane & 15);
    const int a_col = (lane >> 4) * 8;
    const int b_row = (lane & 15);
    const int b_col = (lane >> 4) * 8;

    float acc[4][4][4];
    #pragma unroll
    for (int i = 0; i < 4; i++)
        #pragma unroll
        for (int j = 0; j < 4; j++)
            #pragma unroll
            for (int e = 0; e < 4; e++) acc[i][j][e] = 0.f;

    load_tile(0, 0);

    for (int t = 0; t < NT_K; t++) {
        if (t + 1 < NT_K) { load_tile((t + 1) & 1, t + 1); CP_WAIT(1); }
        else              { CP_WAIT(0); }
        __syncthreads();

        const unsigned abase = sb + (unsigned)(t & 1) * (ST_H * 2);
        const unsigned bbase = abase + A_HS * 2;

        #pragma unroll
        for (int kc = 0; kc < 4; kc++) {
            unsigned af[4][4], bf[2][4];
            #pragma unroll
            for (int mt = 0; mt < 4; mt++)
                ldsm_x4(af[mt], abase +
                    ((warpM + mt * 16 + a_row) * LDA_H + kc * 16 + a_col) * 2);
            #pragma unroll
            for (int ntp = 0; ntp < 2; ntp++)
                ldsm_x4_t(bf[ntp], bbase +
                    ((kc * 16 + b_row) * LDB_H + warpN + ntp * 16 + b_col) * 2);
            #pragma unroll
            for (int mt = 0; mt < 4; mt++)
                #pragma unroll
                for (int nt = 0; nt < 4; nt++)
                    mma_f16(acc[mt][nt], af[mt], &bf[nt >> 1][(nt & 1) * 2]);
        }
        __syncthreads();
    }

    #pragma unroll
    for (int mt = 0; mt < 4; mt++) {
        #pragma unroll
        for (int nt = 0; nt < 4; nt++) {
            int r = bm + warpM + mt * 16 + g;
            int cN = bn + warpN + nt * 8 + tg * 2;
            *(float2*)(C + (size_t)r * N + cN) = make_float2(acc[mt][nt][0], acc[mt][nt][1]);
            *(float2*)(C + (size_t)(r + 8) * N + cN) = make_float2(acc[mt][nt][2], acc[mt][nt][3]);
        }
    }
}

// ================= beta / g projections (32 rows per block) ================
__global__ __launch_bounds__(256) void proj_ba_kernel(
    const float* __restrict__ x, const float* __restrict__ w_b,
    const float* __restrict__ w_a, const float* __restrict__ dt_bias,
    const float* __restrict__ A_log)
{
    __shared__ float sx[32][64];
    const int row0 = blockIdx.x * 32;
    const int tid = threadIdx.x;
    const int col = tid & 63;
    const int isa = (col >= 32);
    const int c32 = col & 31;
    const int rg = tid >> 6;
    const float* w = isa ? w_a : w_b;

    float acc[8];
    #pragma unroll
    for (int j = 0; j < 8; j++) acc[j] = 0.f;

    for (int k0 = 0; k0 < Dv; k0 += 64) {
        __syncthreads();
        #pragma unroll
        for (int i = 0; i < 2; i++) {
            int e = (tid + i * 256) * 4;
            int r = e >> 6, c = e & 63;
            *(float4*)&sx[r][c] = *(const float4*)(x + (size_t)(row0 + r) * Dv + k0 + c);
        }
        __syncthreads();
        for (int kk = 0; kk < 64; kk++) {
            float wv = w[(k0 + kk) * HVv + c32];
            #pragma unroll
            for (int j = 0; j < 8; j++)
                acc[j] += sx[rg * 8 + j][kk] * wv;
        }
    }
    #pragma unroll
    for (int j = 0; j < 8; j++) {
        int r = row0 + rg * 8 + j;
        if (!isa) {
            g_beta[r * HVv + c32] = 1.f / (1.f + expf(-acc[j]));
        } else {
            float xsp = acc[j] + dt_bias[c32];
            float sp = (xsp > 20.f) ? xsp : log1pf(expf(xsp));
            g_gg[r * HVv + c32] = -expf(A_log[c32]) * sp;
        }
    }
}

// ================= causal conv (v channels only) + SiLU ====================
__global__ void conv_v_kernel(const float* __restrict__ conv_w)
{
    const int n4 = BT * VALUE_DIM / 4;
    int idx = blockIdx.x * blockDim.x + threadIdx.x;
    if (idx >= n4) return;
    const int c4 = idx % (VALUE_DIM / 4);
    const int bt = idx / (VALUE_DIM / 4);
    const int t = bt % Tv;
    const int coff = 2 * KEY_DIM / 4 + c4;

    float4 acc = make_float4(0.f, 0.f, 0.f, 0.f);
    #pragma unroll
    for (int k = 0; k < KCONV; k++) {
        int tt = t + k - (KCONV - 1);
        if (tt >= 0) {
            float4 m = ((const float4*)g_mixed)[(size_t)(bt + k - (KCONV - 1)) * (CONV_DIM / 4) + coff];
            float4 w = ((const float4*)conv_w)[k * (CONV_DIM / 4) + coff];
            acc.x += m.x * w.x;
            acc.y += m.y * w.y;
            acc.z += m.z * w.z;
            acc.w += m.w * w.w;
        }
    }
    acc.x = acc.x / (1.f + expf(-acc.x));
    acc.y = acc.y / (1.f + expf(-acc.y));
    acc.z = acc.z / (1.f + expf(-acc.z));
    acc.w = acc.w / (1.f + expf(-acc.w));
    ((float4*)g_mixedc)[(size_t)bt * (CONV_DIM / 4) + coff] = acc;
}

// ================= fused conv + SiLU + l2norm for q/k heads ================
__global__ void conv_qk_norm_kernel(const float* __restrict__ conv_w)
{
    const int gw = (blockIdx.x * blockDim.x + threadIdx.x) >> 5;
    const int lane = threadIdx.x & 31;
    const int bt = gw >> 5;
    const int r = gw & 31;
    const int isk = r >> 4;
    const int h = r & 15;
    const int t = bt % Tv;
    const int cbase = isk * KEY_DIM + h * DKv;

    float v[4];
    float ss = 0.f;
    #pragma unroll
    for (int i = 0; i < 4; i++) {
        const int c = cbase + lane + 32 * i;
        float acc = 0.f;
        #pragma unroll
        for (int k = 0; k < KCONV; k++) {
            int tt = t + k - (KCONV - 1);
            if (tt >= 0)
                acc += g_mixed[(size_t)(bt + k - (KCONV - 1)) * CONV_DIM + c]
                     * conv_w[k * CONV_DIM + c];
        }
        float s = acc / (1.f + expf(-acc));
        v[i] = s;
        ss += s * s;
    }
    #pragma unroll
    for (int off = 16; off > 0; off >>= 1)
        ss += __shfl_xor_sync(0xFFFFFFFFu, ss, off);
    float sc = rsqrtf(ss + EPSv);
    if (!isk) sc *= 0.08838834764831845f;
    float* dst = (isk ? g_kn : g_qn) + ((size_t)bt * HKv + h) * DKv;
    #pragma unroll
    for (int i = 0; i < 4; i++) dst[lane + 32 * i] = v[i] * sc;
}

// ================= sequential gated delta-rule scan (f32x2, 2 steps/bar) ===
__global__ __launch_bounds__(128, 1) void scan_kernel()
{
    const int unit = blockIdx.x >> 1;
    const int chalf = blockIdx.x & 1;
    const int b = unit / HVv;
    const int h = unit % HVv;
    const int kvh = h >> 1;

    const int tid = threadIdx.x;
    const int colL = tid >> 1;
    const int dhalf = tid & 1;
    const int gcol = chalf * 64 + colL;

    ull st2[32];
    #pragma unroll
    for (int i = 0; i < 32; i++) st2[i] = 0ull;

    __shared__ float sq[4][DKv];
    __shared__ float sk[4][DKv];
    __shared__ float sv[4][64];

    const size_t qkbase0 = ((size_t)(b * Tv) * HKv + kvh) * DKv;
    const size_t vbase0 = (size_t)(b * Tv) * CONV_DIM + 2 * KEY_DIM + h * DVv;
    const size_t corebase = ((size_t)(b * Tv) * HVv + h) * DVv + gcol;

    float rq0 = g_qn[qkbase0 + tid];
    float rk0 = g_kn[qkbase0 + tid];
    float rv0 = (tid < 64) ? g_mixedc[vbase0 + chalf * 64 + tid] : 0.f;
    float rg0 = g_gg[(b * Tv) * HVv + h];
    float rb0 = g_beta[(b * Tv) * HVv + h];
    float rq1 = g_qn[qkbase0 + HKv * DKv + tid];
    float rk1 = g_kn[qkbase0 + HKv * DKv + tid];
    float rv1 = (tid < 64) ? g_mixedc[vbase0 + CONV_DIM + chalf * 64 + tid] : 0.f;
    float rg1 = g_gg[(b * Tv + 1) * HVv + h];
    float rb1 = g_beta[(b * Tv + 1) * HVv + h];

    auto do_step = [&](int buf, float dec, float be, int tg2) {
        const ull dec2 = pack2(dec, dec);
        const ulonglong2* kp = (const ulonglong2*)&sk[buf][dhalf * 64];
        ull kreg[32];
        #pragma unroll
        for (int j = 0; j < 16; j++) {
            ulonglong2 kk = kp[j];
            kreg[2 * j] = kk.x;
            kreg[2 * j + 1] = kk.y;
        }
        ull kva = 0ull, kvb = 0ull, kvc = 0ull, kvd = 0ull;
        #pragma unroll
        for (int i = 0; i < 32; i += 4) {
            st2[i]     = mul2(st2[i],     dec2);
            st2[i + 1] = mul2(st2[i + 1], dec2);
            st2[i + 2] = mul2(st2[i + 2], dec2);
            st2[i + 3] = mul2(st2[i + 3], dec2);
            kva = fma2(kreg[i],     st2[i],     kva);
            kvb = fma2(kreg[i + 1], st2[i + 1], kvb);
            kvc = fma2(kreg[i + 2], st2[i + 2], kvc);
            kvd = fma2(kreg[i + 3], st2[i + 3], kvd);
        }
        ull kvp = add2(add2(kva, kvb), add2(kvc, kvd));
        float klo, khi;
        unpack2(klo, khi, kvp);
        float kv = klo + khi;
        kv += __shfl_xor_sync(0xFFFFFFFFu, kv, 1);

        const float vt = sv[buf][colL];
        const float delta = (vt - kv) * be;
        const ull delta2 = pack2(delta, delta);

        const ulonglong2* qp = (const ulonglong2*)&sq[buf][dhalf * 64];
        ull oa = 0ull, ob = 0ull, oc = 0ull, od = 0ull;
        #pragma unroll
        for (int j = 0; j < 8; j++) {
            ulonglong2 q0 = qp[2 * j];
            ulonglong2 q1 = qp[2 * j + 1];
            int i = 4 * j;
            st2[i]     = fma2(kreg[i],     delta2, st2[i]);
            st2[i + 1] = fma2(kreg[i + 1], delta2, st2[i + 1]);
            st2[i + 2] = fma2(kreg[i + 2], delta2, st2[i + 2]);
            st2[i + 3] = fma2(kreg[i + 3], delta2, st2[i + 3]);
            oa = fma2(q0.x, st2[i],     oa);
            ob = fma2(q0.y, st2[i + 1], ob);
            oc = fma2(q1.x, st2[i + 2], oc);
            od = fma2(q1.y, st2[i + 3], od);
        }
        ull op = add2(add2(oa, ob), add2(oc, od));
        float olo, ohi;
        unpack2(olo, ohi, op);
        float out = olo + ohi;
        out += __shfl_xor_sync(0xFFFFFFFFu, out, 1);
        if (dhalf == 0)
            g_core[corebase + (size_t)tg2 * (HVv * DVv)] = out;
    };

    for (int t = 0; t < Tv; t += 2) {
        const int b0 = ((t >> 1) & 1) * 2;
        const int b1 = b0 + 1;
        sq[b0][tid] = rq0; sk[b0][tid] = rk0;
        sq[b1][tid] = rq1; sk[b1][tid] = rk1;
        if (tid < 64) { sv[b0][tid] = rv0; sv[b1][tid] = rv1; }
        const float gt0 = rg0, be0 = rb0, gt1 = rg1, be1 = rb1;
        __syncthreads();

        const int tn0 = (t + 2 < Tv) ? (t + 2) : t;
        const int tn1 = (t + 3 < Tv) ? (t + 3) : t;
        {
            const size_t qkb0 = qkbase0 + (size_t)tn0 * (HKv * DKv);
            const size_t qkb1 = qkbase0 + (size_t)tn1 * (HKv * DKv);
            rq0 = g_qn[qkb0 + tid]; rk0 = g_kn[qkb0 + tid];
            rq1 = g_qn[qkb1 + tid]; rk1 = g_kn[qkb1 + tid];
            if (tid < 64) {
                rv0 = g_mixedc[vbase0 + (size_t)tn0 * CONV_DIM + chalf * 64 + tid];
                rv1 = g_mixedc[vbase0 + (size_t)tn1 * CONV_DIM + chalf * 64 + tid];
            }
            rg0 = g_gg[(b * Tv + tn0) * HVv + h];
            rb0 = g_beta[(b * Tv + tn0) * HVv + h];
            rg1 = g_gg[(b * Tv + tn1) * HVv + h];
            rb1 = g_beta[(b * Tv + tn1) * HVv + h];
        }

        const float dec0 = expf(gt0);
        const float dec1 = expf(gt1);
        do_step(b0, dec0, be0, t);
        do_step(b1, dec1, be1, t + 1);
    }
}

// ================= gated RMS norm epilogue (writes fp16) ====================
__global__ void gate_kernel(const float* __restrict__ norm_w)
{
    const int row = (blockIdx.x * blockDim.x + threadIdx.x) >> 5;
    const int lane = threadIdx.x & 31;
    const int bt = row / HVv;
    const int h = row % HVv;

    const float* c = g_core + (size_t)row * DVv;
    __half* ch = g_coreh + (size_t)row * DVv;
    const float* z = g_z + (size_t)bt * VALUE_DIM + h * DVv;

    float v[4];
    float ss = 0.f;
    #pragma unroll
    for (int i = 0; i < 4; i++) {
        v[i] = c[lane + 32 * i];
        ss += v[i] * v[i];
    }
    #pragma unroll
    for (int off = 16; off > 0; off >>= 1)
        ss += __shfl_xor_sync(0xFFFFFFFFu, ss, off);
    float rinv = rsqrtf(ss * (1.f / 128.f) + EPSv);
    #pragma unroll
    for (int i = 0; i < 4; i++) {
        int idx = lane + 32 * i;
        float zv = z[idx];
        float sig = 1.f / (1.f + expf(-zv));
        ch[idx] = __float2half_rn(norm_w[idx] * v[i] * rinv * zv * sig);
    }
}

// ================= launch ==================================================
extern "C" void kernel_launch(void* const* d_in, const int* in_sizes, int n_in,
                              void* d_out, int out_size)
{
    const float* x       = (const float*)d_in[0];
    const float* w_qkv   = (const float*)d_in[1];
    const float* w_z     = (const float*)d_in[2];
    const float* w_b     = (const float*)d_in[3];
    const float* w_a     = (const float*)d_in[4];
    const float* conv_w  = (const float*)d_in[5];
    const float* dt_bias = (const float*)d_in[6];
    const float* A_log   = (const float*)d_in[7];
    const float* norm_w  = (const float*)d_in[8];
    const float* w_out   = (const float*)d_in[9];
    float* out = (float*)d_out;

    float *mixed, *z, *core;
    __half *xh, *wqkvh, *wzh, *wouth, *coreh;
    cudaGetSymbolAddress((void**)&mixed, g_mixed);
    cudaGetSymbolAddress((void**)&z,     g_z);
    cudaGetSymbolAddress((void**)&core,  g_core);
    cudaGetSymbolAddress((void**)&xh,    g_xh);
    cudaGetSymbolAddress((void**)&wqkvh, g_wqkvh);
    cudaGetSymbolAddress((void**)&wzh,   g_wzh);
    cudaGetSymbolAddress((void**)&wouth, g_wouth);
    cudaGetSymbolAddress((void**)&coreh, g_coreh);

    cudaFuncSetAttribute(hgemm_kernel,
                         cudaFuncAttributeMaxDynamicSharedMemorySize, GEMM_SMEM);

    static cudaStream_t s1 = nullptr, s2 = nullptr;
    static cudaEvent_t ev0 = nullptr, ev_fx = nullptr, ev_wq = nullptr,
                       ev_g1 = nullptr, ev_cv = nullptr, ev_z = nullptr, ev_ba = nullptr;
    if (s1 == nullptr) {
        cudaStreamCreateWithFlags(&s1, cudaStreamNonBlocking);
        cudaStreamCreateWithFlags(&s2, cudaStreamNonBlocking);
        cudaEventCreateWithFlags(&ev0,   cudaEventDisableTiming);
        cudaEventCreateWithFlags(&ev_fx, cudaEventDisableTiming);
        cudaEventCreateWithFlags(&ev_wq, cudaEventDisableTiming);
        cudaEventCreateWithFlags(&ev_g1, cudaEventDisableTiming);
        cudaEventCreateWithFlags(&ev_cv, cudaEventDisableTiming);
        cudaEventCreateWithFlags(&ev_z,  cudaEventDisableTiming);
        cudaEventCreateWithFlags(&ev_ba, cudaEventDisableTiming);
    }

    // ---- s0: fork origin
    cudaEventRecord(ev0, 0);

    // ---- s2 (forked at t=0): w_qkv -> fp16, then proj_ba + w_out conversion
    cudaStreamWaitEvent(s2, ev0, 0);
    f2h_kernel<<<(Dv * CONV_DIM / 8 + 255) / 256, 256, 0, s2>>>(w_qkv, wqkvh, Dv * CONV_DIM / 8);
    cudaEventRecord(ev_wq, s2);
    proj_ba_kernel<<<BT / 32, 256, 0, s2>>>(x, w_b, w_a, dt_bias, A_log);
    f2h_kernel<<<(VALUE_DIM * Dv / 8 + 255) / 256, 256, 0, s2>>>(w_out, wouth, VALUE_DIM * Dv / 8);
    cudaEventRecord(ev_ba, s2);

    // ---- s0: x -> fp16
    f2h_kernel<<<(BT * Dv / 8 + 255) / 256, 256>>>(x, xh, BT * Dv / 8);
    cudaEventRecord(ev_fx, 0);

    // ---- s1 (fork): w_z -> fp16, GEMM2 (z)
    cudaStreamWaitEvent(s1, ev_fx, 0);
    f2h_kernel<<<(Dv * VALUE_DIM / 8 + 255) / 256, 256, 0, s1>>>(w_z, wzh, Dv * VALUE_DIM / 8);
    hgemm_kernel<<<dim3(VALUE_DIM / 128, BT / 128), 256, GEMM_SMEM, s1>>>(xh, wzh, z, BT, VALUE_DIM, Dv);
    cudaEventRecord(ev_z, s1);

    // ---- s0 main chain: GEMM1
    cudaStreamWaitEvent(0, ev_wq, 0);
    hgemm_kernel<<<dim3(CONV_DIM / 128, BT / 128), 256, GEMM_SMEM>>>(xh, wqkvh, mixed, BT, CONV_DIM, Dv);
    cudaEventRecord(ev_g1, 0);

    // ---- s2: conv_v concurrent with conv_qk_norm (both DRAM-bound)
    cudaStreamWaitEvent(s2, ev_g1, 0);
    conv_v_kernel<<<(BT * VALUE_DIM / 4 + 255) / 256, 256, 0, s2>>>(conv_w);
    cudaEventRecord(ev_cv, s2);

    // ---- s0: conv_qk_norm, then scan (needs conv_v + g/beta too)
    conv_qk_norm_kernel<<<BT * 32 * 32 / 256, 256>>>(conv_w);

    cudaStreamWaitEvent(0, ev_cv, 0);
    cudaStreamWaitEvent(0, ev_ba, 0);
    scan_kernel<<<Bv * HVv * 2, 128>>>();

    cudaStreamWaitEvent(0, ev_z, 0);           // gate needs z
    gate_kernel<<<BT * HVv / 8, 256>>>(norm_w);

    hgemm_kernel<<<dim3(Dv / 128, BT / 128), 256, GEMM_SMEM>>>(coreh, wouth, out, BT, Dv, VALUE_DIM);
}